// round 13
// baseline (speedup 1.0000x reference)
#include <cuda_runtime.h>
#include <cuda_fp16.h>
#include <math.h>

#define BATCH  2
#define SEQ    2048
#define DMODEL 256
#define DINNER 512
#define DSTATE 16
#define NTOK   (BATCH*SEQ)   // 4096
#define NSEG   8
#define SEGLEN (SEQ/NSEG)    // 256
#define NCHAIN (BATCH*DINNER*DSTATE)  // 16384

// ---------------- scratch ----------------
__device__ __half g_hn_h[NTOK*DMODEL];
__device__ float  g_xz[NTOK*2*DINNER];
__device__ float  g_xc[NTOK*DINNER];
__device__ float  g_dbl[NTOK*48];
__device__ float  g_ddx[NTOK*DINNER*2];    // (delta, delta*xc) pairs
__device__ __half g_yact_h[NTOK*DINNER];
__device__ __half g_win_h[2*DINNER*DMODEL];
__device__ __half g_wout_h[DMODEL*DINNER];
__device__ __half g_wxp_h[48*DINNER];
__device__ float  g_scanH[NSEG*NCHAIN];
__device__ float  g_scanP[NSEG*NCHAIN];

__device__ __forceinline__ void cpa16(unsigned dst, const void* src) {
    asm volatile("cp.async.ca.shared.global [%0], [%1], 16;\n" :: "r"(dst), "l"(src));
}
template<int N> __device__ __forceinline__ void waitg() {
    asm volatile("cp.async.wait_group %0;\n" :: "n"(N));
}

// ---------------- 1) RMSNorm + weight cvt ----------------
__global__ __launch_bounds__(256) void rmsnorm_cvt_kernel(
    const float* __restrict__ x, const float* __restrict__ nw,
    const float* __restrict__ win, const float* __restrict__ wout,
    const float* __restrict__ wxp)
{
    {
        int stride = 128*256;
        for (int i = blockIdx.x*256 + threadIdx.x; i < 2*DINNER*DMODEL; i += stride)
            g_win_h[i] = __float2half(win[i]);
        for (int i = blockIdx.x*256 + threadIdx.x; i < DMODEL*DINNER; i += stride)
            g_wout_h[i] = __float2half(wout[i]);
        for (int i = blockIdx.x*256 + threadIdx.x; i < 48*DINNER; i += stride)
            g_wxp_h[i] = __float2half(wxp[i]);
    }

    int l0 = blockIdx.x * 32;
    int b  = l0 >> 11;
    int lb = l0 & 2047;
    int w    = threadIdx.x >> 5;
    int lane = threadIdx.x & 31;

    __shared__ float st[256*33];
    __shared__ float ssum[32][9];
    __shared__ float rs[32];

    const float* xb = x + (size_t)b * DMODEL * SEQ + lb + lane;

    float vals[32];
    float ss = 0.f;
    #pragma unroll
    for (int ci = 0; ci < 32; ci++) {
        int c = ci*8 + w;
        float v = xb[(size_t)c * SEQ];
        vals[ci] = v;
        ss += v*v;
    }
    ssum[lane][w] = ss;
    __syncthreads();
    if (threadIdx.x < 32) {
        float tot = 0.f;
        #pragma unroll
        for (int j = 0; j < 8; j++) tot += ssum[threadIdx.x][j];
        rs[threadIdx.x] = rsqrtf(tot * (1.0f/DMODEL) + 1e-5f);
    }
    #pragma unroll
    for (int ci = 0; ci < 32; ci++)
        st[(ci*8 + w)*33 + lane] = vals[ci];
    __syncthreads();

    #pragma unroll
    for (int p = 0; p < 4; p++) {
        int t = (threadIdx.x >> 5) + p*8;
        float r = rs[t];
        __half* orow = g_hn_h + (size_t)(l0 + t)*DMODEL;
        #pragma unroll
        for (int j = 0; j < 8; j++) {
            int c = lane + j*32;
            orow[c] = __float2half(st[c*33 + t] * r * nw[c]);
        }
    }
}

// ---------------- fp16 tensor-core GEMM (3-deep cp.async pipeline) ----------
#define HBUF 3840

template<int MODE>
__global__ __launch_bounds__(256) void mma_pipe_h(
    const __half* __restrict__ A, const __half* __restrict__ Bw,
    float* __restrict__ C, int K, int N, const float* __restrict__ resid)
{
    extern __shared__ __align__(16) unsigned sm[];
    int tid  = threadIdx.x;
    int lane = tid & 31, w = tid >> 5;
    int wm = w & 3, wn = w >> 2;
    int rowBase = blockIdx.x * 128;
    int colBase = blockIdx.y * 64;

    int arow = tid >> 1, aseg = tid & 1;
    int brow = tid >> 2, bseg = tid & 3;
    const __half* Ag = A  + (size_t)(rowBase + arow)*K + aseg*16;
    const __half* Bg = Bw + (size_t)(colBase + brow)*K + bseg*8;

    float acc[2][4][4];
    #pragma unroll
    for (int mt = 0; mt < 2; mt++)
        #pragma unroll
        for (int nt = 0; nt < 4; nt++)
            #pragma unroll
            for (int q = 0; q < 4; q++) acc[mt][nt][q] = 0.f;

    unsigned sbase = (unsigned)__cvta_generic_to_shared(sm);

    auto issue = [&](int kt, int buf) {
        unsigned ab = sbase + (unsigned)buf*15360u;
        cpa16(ab + (unsigned)(arow*80 + aseg*32),      Ag + kt);
        cpa16(ab + (unsigned)(arow*80 + aseg*32 + 16), Ag + kt + 8);
        cpa16(ab + 10240u + (unsigned)(brow*80 + bseg*16), Bg + kt);
        asm volatile("cp.async.commit_group;\n");
    };

    int CH = K >> 5;
    issue(0, 0);
    if (CH > 1) issue(32, 1);

    for (int c = 0; c < CH; c++) {
        if (c + 2 < CH) {
            issue((c+2)*32, (c+2)%3);
            waitg<2>();
        } else if (c + 1 < CH) {
            waitg<1>();
        } else {
            waitg<0>();
        }
        __syncthreads();

        const unsigned* Asw = sm + (c%3)*HBUF;
        const unsigned* Bsw = Asw + 2560;

        #pragma unroll
        for (int ks = 0; ks < 2; ks++) {
            int kw = ks*8;
            unsigned a[2][4], bq[4][2];
            #pragma unroll
            for (int mt = 0; mt < 2; mt++) {
                int r0 = wm*32 + mt*16 + (lane >> 2);
                int bi = r0*20 + kw + (lane & 3);
                a[mt][0] = Asw[bi];
                a[mt][1] = Asw[bi + 160];
                a[mt][2] = Asw[bi + 4];
                a[mt][3] = Asw[bi + 164];
            }
            #pragma unroll
            for (int nt = 0; nt < 4; nt++) {
                int n0 = wn*32 + nt*8 + (lane >> 2);
                int bb = n0*20 + kw + (lane & 3);
                bq[nt][0] = Bsw[bb];
                bq[nt][1] = Bsw[bb + 4];
            }
            #pragma unroll
            for (int mt = 0; mt < 2; mt++)
                #pragma unroll
                for (int nt = 0; nt < 4; nt++)
                    asm volatile(
                        "mma.sync.aligned.m16n8k16.row.col.f32.f16.f16.f32 "
                        "{%0,%1,%2,%3}, {%4,%5,%6,%7}, {%8,%9}, {%0,%1,%2,%3};"
                        : "+f"(acc[mt][nt][0]), "+f"(acc[mt][nt][1]),
                          "+f"(acc[mt][nt][2]), "+f"(acc[mt][nt][3])
                        : "r"(a[mt][0]), "r"(a[mt][1]), "r"(a[mt][2]), "r"(a[mt][3]),
                          "r"(bq[nt][0]), "r"(bq[nt][1]));
        }
    }

    if (MODE == 0) {
        #pragma unroll
        for (int mt = 0; mt < 2; mt++) {
            #pragma unroll
            for (int nt = 0; nt < 4; nt++) {
                int r0 = rowBase + wm*32 + mt*16 + (lane >> 2);
                int c0 = colBase + wn*32 + nt*8 + (lane & 3)*2;
                *(float2*)&C[(size_t)r0*N + c0] =
                    make_float2(acc[mt][nt][0], acc[mt][nt][1]);
                *(float2*)&C[(size_t)(r0+8)*N + c0] =
                    make_float2(acc[mt][nt][2], acc[mt][nt][3]);
            }
        }
    } else {
        __syncthreads();   // protect smem: other warps may still read As/Bs
        float* tr = (float*)sm;
        #pragma unroll
        for (int mt = 0; mt < 2; mt++) {
            #pragma unroll
            for (int nt = 0; nt < 4; nt++) {
                int r  = wm*32 + mt*16 + (lane >> 2);
                int cl = wn*32 + nt*8 + (lane & 3)*2;
                tr[ cl   *132 + r    ] = acc[mt][nt][0];
                tr[(cl+1)*132 + r    ] = acc[mt][nt][1];
                tr[ cl   *132 + r + 8] = acc[mt][nt][2];
                tr[(cl+1)*132 + r + 8] = acc[mt][nt][3];
            }
        }
        __syncthreads();
        int b0 = rowBase >> 11;
        int lbase = rowBase & 2047;
        for (int i = tid; i < 64*32; i += 256) {
            int cl = i >> 5, j = i & 31;
            float4 v = *(float4*)&tr[cl*132 + j*4];
            size_t o = (size_t)b0*DMODEL*SEQ + (size_t)(colBase + cl)*SEQ + lbase + j*4;
            float4 rr = *(const float4*)&resid[o];
            v.x += rr.x; v.y += rr.y; v.z += rr.z; v.w += rr.w;
            *(float4*)&C[o] = v;
        }
    }
}

// ---------------- x_proj fused with conv+SiLU + delta/ddx epilogue ----------
#define XPB 260

__global__ __launch_bounds__(256) void xproj_conv_kernel(
    const float* __restrict__ cw, const float* __restrict__ cb,
    const float* __restrict__ dtW, const float* __restrict__ dtB)
{
    extern __shared__ __align__(16) unsigned xsm[];
    unsigned* Bs = xsm;
    unsigned* As = xsm + 48*XPB;
    __shared__ __align__(16) float sdt[16][20];

    int tid = threadIdx.x, lane = tid & 31, w = tid >> 5;
    int rowBase = blockIdx.x * 16;
    int l0 = rowBase & 2047;

    {
        unsigned bbase = (unsigned)__cvta_generic_to_shared(Bs);
        #pragma unroll
        for (int k = 0; k < 12; k++) {
            int i = tid + k*256;
            int n = i >> 6;
            int hw = (i & 63) * 4;
            cpa16(bbase + (unsigned)((n*XPB + hw)*4),
                  g_wxp_h + (size_t)n*DINNER + hw*2);
        }
        asm volatile("cp.async.commit_group;\n");
    }

    int tA = tid >> 4;
    int dOff = (tid & 15) * 2;
    int gt = rowBase + tA;

    float2 v[4];
    #pragma unroll
    for (int j = 0; j < 4; j++) {
        int ls = l0 + tA - 3 + j;
        v[j] = (ls >= 0) ? *(const float2*)(g_xz + (size_t)(gt-3+j)*1024 + dOff)
                         : make_float2(0.f, 0.f);
    }

    float acc[4] = {0.f, 0.f, 0.f, 0.f};

    waitg<0>();
    __syncthreads();

    for (int c = 0; c < 16; c++) {
        int d = c*32 + dOff;
        float4 w0 = *(const float4*)(cw + (size_t)d*4);
        float4 w1 = *(const float4*)(cw + (size_t)(d+1)*4);
        float2 a2 = *(const float2*)(cb + d);
        a2.x += w0.x*v[0].x + w0.y*v[1].x + w0.z*v[2].x + w0.w*v[3].x;
        a2.y += w1.x*v[0].y + w1.y*v[1].y + w1.z*v[2].y + w1.w*v[3].y;
        a2.x = a2.x / (1.f + __expf(-a2.x));
        a2.y = a2.y / (1.f + __expf(-a2.y));
        *(float2*)(g_xc + (size_t)gt*DINNER + d) = a2;

        unsigned* Ab = As + (c & 1)*320;
        __half2 p = __floats2half2_rn(a2.x, a2.y);
        Ab[tA*20 + (tid & 15)] = *(unsigned*)&p;

        if (c + 1 < 16) {
            int dn = (c+1)*32 + dOff;
            #pragma unroll
            for (int j = 0; j < 4; j++) {
                int ls = l0 + tA - 3 + j;
                v[j] = (ls >= 0) ? *(const float2*)(g_xz + (size_t)(gt-3+j)*1024 + dn)
                                 : make_float2(0.f, 0.f);
            }
        }
        __syncthreads();

        if (w < 6) {
            const unsigned* Asw = As + (c & 1)*320;
            #pragma unroll
            for (int ks = 0; ks < 2; ks++) {
                int kw = ks*8;
                unsigned a[4], bq[2];
                {
                    int r0 = lane >> 2;
                    int bi = r0*20 + kw + (lane & 3);
                    a[0] = Asw[bi];
                    a[1] = Asw[bi + 160];
                    a[2] = Asw[bi + 4];
                    a[3] = Asw[bi + 164];
                }
                {
                    int n0 = w*8 + (lane >> 2);
                    int bb = n0*XPB + c*16 + kw + (lane & 3);
                    bq[0] = Bs[bb];
                    bq[1] = Bs[bb + 4];
                }
                asm volatile(
                    "mma.sync.aligned.m16n8k16.row.col.f32.f16.f16.f32 "
                    "{%0,%1,%2,%3}, {%4,%5,%6,%7}, {%8,%9}, {%0,%1,%2,%3};"
                    : "+f"(acc[0]), "+f"(acc[1]), "+f"(acc[2]), "+f"(acc[3])
                    : "r"(a[0]), "r"(a[1]), "r"(a[2]), "r"(a[3]),
                      "r"(bq[0]), "r"(bq[1]));
            }
        }
    }

    if (w < 6) {
        int r0 = rowBase + (lane >> 2);
        int c0 = w*8 + (lane & 3)*2;
        *(float2*)&g_dbl[(size_t)r0*48 + c0] = make_float2(acc[0], acc[1]);
        *(float2*)&g_dbl[(size_t)(r0+8)*48 + c0] = make_float2(acc[2], acc[3]);
    }
    if (w < 2) {
        int tloc = lane >> 2;
        int c0 = w*8 + (lane & 3)*2;
        sdt[tloc    ][c0] = acc[0]; sdt[tloc    ][c0+1] = acc[1];
        sdt[tloc + 8][c0] = acc[2]; sdt[tloc + 8][c0+1] = acc[3];
    }
    __syncthreads();

    {
        int d2 = tid * 2;
        const float4* wr0 = (const float4*)(dtW + (size_t)d2*16);
        const float4* wr1 = (const float4*)(dtW + (size_t)(d2+1)*16);
        float4 A0 = wr0[0], A1 = wr0[1], A2 = wr0[2], A3 = wr0[3];
        float4 B0 = wr1[0], B1 = wr1[1], B2 = wr1[2], B3 = wr1[3];
        float b0 = dtB[d2], b1 = dtB[d2+1];
        #pragma unroll 4
        for (int t = 0; t < 16; t++) {
            const float4* sp = (const float4*)&sdt[t][0];
            float4 r0 = sp[0], r1 = sp[1], r2 = sp[2], r3 = sp[3];
            float a0 = b0, a1 = b1;
            a0 = fmaf(r0.x,A0.x,a0); a0 = fmaf(r0.y,A0.y,a0); a0 = fmaf(r0.z,A0.z,a0); a0 = fmaf(r0.w,A0.w,a0);
            a0 = fmaf(r1.x,A1.x,a0); a0 = fmaf(r1.y,A1.y,a0); a0 = fmaf(r1.z,A1.z,a0); a0 = fmaf(r1.w,A1.w,a0);
            a0 = fmaf(r2.x,A2.x,a0); a0 = fmaf(r2.y,A2.y,a0); a0 = fmaf(r2.z,A2.z,a0); a0 = fmaf(r2.w,A2.w,a0);
            a0 = fmaf(r3.x,A3.x,a0); a0 = fmaf(r3.y,A3.y,a0); a0 = fmaf(r3.z,A3.z,a0); a0 = fmaf(r3.w,A3.w,a0);
            a1 = fmaf(r0.x,B0.x,a1); a1 = fmaf(r0.y,B0.y,a1); a1 = fmaf(r0.z,B0.z,a1); a1 = fmaf(r0.w,B0.w,a1);
            a1 = fmaf(r1.x,B1.x,a1); a1 = fmaf(r1.y,B1.y,a1); a1 = fmaf(r1.z,B1.z,a1); a1 = fmaf(r1.w,B1.w,a1);
            a1 = fmaf(r2.x,B2.x,a1); a1 = fmaf(r2.y,B2.y,a1); a1 = fmaf(r2.z,B2.z,a1); a1 = fmaf(r2.w,B2.w,a1);
            a1 = fmaf(r3.x,B3.x,a1); a1 = fmaf(r3.y,B3.y,a1); a1 = fmaf(r3.z,B3.z,a1); a1 = fmaf(r3.w,B3.w,a1);
            a0 = (a0 > 20.f) ? a0 : log1pf(__expf(a0));
            a1 = (a1 > 20.f) ? a1 : log1pf(__expf(a1));
            float2 xcv = *(const float2*)(g_xc + (size_t)(rowBase + t)*DINNER + d2);
            float4 o = make_float4(a0, a0 * xcv.x, a1, a1 * xcv.y);
            *(float4*)(g_ddx + ((size_t)(rowBase + t)*DINNER + d2)*2) = o;
        }
    }
}

// ---------------- segmented selective scan (2-phase, fused carry) -----------
__global__ __launch_bounds__(128) void scan_part1(const float* __restrict__ A_log)
{
    int b   = blockIdx.z;
    int seg = blockIdx.y;
    int d0  = blockIdx.x * 8;
    int tid = threadIdx.x;
    int dl  = tid >> 4, n = tid & 15;
    int d   = d0 + dl;

    float a = -expf(A_log[d*DSTATE + n]);
    float h = 0.f, S = 0.f;

    __shared__ __align__(16) float sB[3][32][20];
    __shared__ __align__(16) float sddx[3][32][16];

    unsigned aB  = (unsigned)__cvta_generic_to_shared(&sB[0][0][0]);
    unsigned adx = (unsigned)__cvta_generic_to_shared(&sddx[0][0][0]);

    auto issue = [&](int ch, int buf) {
        int base = b*SEQ + seg*SEGLEN + ch*32;
        {
            int t = tid >> 2, s = tid & 3;
            cpa16(aB + (unsigned)((buf*32*20 + t*20 + s*4)*4),
                  g_dbl + (size_t)(base + t)*48 + 16 + s*4);
            cpa16(adx + (unsigned)((buf*32*16 + t*16 + s*4)*4),
                  g_ddx + ((size_t)(base + t)*DINNER + d0)*2 + s*4);
        }
        asm volatile("cp.async.commit_group;\n");
    };

    issue(0, 0);
    issue(1, 1);

    for (int ch = 0; ch < SEGLEN/32; ch++) {
        if (ch + 2 < SEGLEN/32) {
            issue(ch + 2, (ch + 2)%3);
            waitg<2>();
        } else if (ch + 1 < SEGLEN/32) {
            waitg<1>();
        } else {
            waitg<0>();
        }
        __syncthreads();
        int buf = ch % 3;

        #pragma unroll
        for (int t = 0; t < 32; t++) {
            float2 ddx = *(const float2*)&sddx[buf][t][dl*2];
            float dA = __expf(ddx.x * a);
            h = fmaf(dA, h, ddx.y * sB[buf][t][n]);
            S += ddx.x;
        }
    }

    int chain = (b*DINNER + d)*DSTATE + n;
    g_scanH[seg*NCHAIN + chain] = h;
    g_scanP[seg*NCHAIN + chain] = __expf(S * a);
}

__global__ __launch_bounds__(128) void scan_part3(
    const float* __restrict__ A_log, const float* __restrict__ Dp)
{
    int b   = blockIdx.z;
    int seg = blockIdx.y;
    int d0  = blockIdx.x * 8;
    int tid = threadIdx.x;
    int dl  = tid >> 4, n = tid & 15;
    int d   = d0 + dl;
    int ddm = tid & 7;

    float a = -expf(A_log[d*DSTATE + n]);
    float Dval = Dp[d0 + ddm];

    __shared__ __align__(16) float sBC[3][32][36];
    __shared__ __align__(16) float sddx[3][32][16];
    __shared__ float sxc[3][32][8];
    __shared__ float sz[3][32][8];
    __shared__ __align__(16) float shc[32][128];

    unsigned aBC = (unsigned)__cvta_generic_to_shared(&sBC[0][0][0]);
    unsigned adx = (unsigned)__cvta_generic_to_shared(&sddx[0][0][0]);
    unsigned axc = (unsigned)__cvta_generic_to_shared(&sxc[0][0][0]);
    unsigned az  = (unsigned)__cvta_generic_to_shared(&sz[0][0][0]);

    auto issue = [&](int ch, int buf) {
        int base = b*SEQ + seg*SEGLEN + ch*32;
        #pragma unroll
        for (int k = 0; k < 2; k++) {
            int i = tid + k*128;
            int t = i >> 3, s = i & 7;
            cpa16(aBC + (unsigned)((buf*32*36 + t*36 + s*4)*4),
                  g_dbl + (size_t)(base + t)*48 + 16 + s*4);
        }
        {
            int t = tid >> 2, s = tid & 3;
            cpa16(adx + (unsigned)((buf*32*16 + t*16 + s*4)*4),
                  g_ddx + ((size_t)(base + t)*DINNER + d0)*2 + s*4);
        }
        if (tid < 64) {
            int t = tid >> 1, hf = tid & 1;
            cpa16(axc + (unsigned)((buf*256 + t*8 + hf*4)*4),
                  g_xc + (size_t)(base + t)*DINNER + d0 + hf*4);
        } else {
            int i = tid - 64;
            int t = i >> 1, hf = i & 1;
            cpa16(az + (unsigned)((buf*256 + t*8 + hf*4)*4),
                  g_xz + (size_t)(base + t)*1024 + DINNER + d0 + hf*4);
        }
        asm volatile("cp.async.commit_group;\n");
    };

    issue(0, 0);
    issue(1, 1);

    // carry prefix: h = fold of segments 0..seg-1 (overlaps with cp.async)
    float h = 0.f;
    {
        int chain = (b*DINNER + d)*DSTATE + n;
        float Pv[NSEG-1], Hv[NSEG-1];
        #pragma unroll
        for (int s = 0; s < NSEG-1; s++) {
            bool m = (s < seg);
            Pv[s] = m ? g_scanP[s*NCHAIN + chain] : 1.f;
            Hv[s] = m ? g_scanH[s*NCHAIN + chain] : 0.f;
        }
        #pragma unroll
        for (int s = 0; s < NSEG-1; s++)
            h = fmaf(Pv[s], h, Hv[s]);
    }

    for (int ch = 0; ch < SEGLEN/32; ch++) {
        if (ch + 2 < SEGLEN/32) {
            issue(ch + 2, (ch + 2)%3);
            waitg<2>();
        } else if (ch + 1 < SEGLEN/32) {
            waitg<1>();
        } else {
            waitg<0>();
        }
        __syncthreads();   // loads ready + prev reduce done (shc safe)
        int buf = ch % 3;

        #pragma unroll
        for (int t = 0; t < 32; t++) {
            float2 ddx = *(const float2*)&sddx[buf][t][dl*2];
            float dA = __expf(ddx.x * a);
            h = fmaf(dA, h, ddx.y * sBC[buf][t][n]);
            shc[t][tid] = h * sBC[buf][t][16 + n];
        }
        __syncthreads();

        #pragma unroll
        for (int k = 0; k < 2; k++) {
            int t = (tid >> 3) + k*16;
            const float4* hp = (const float4*)&shc[t][ddm*16];
            float4 s0 = hp[0], s1 = hp[1], s2 = hp[2], s3 = hp[3];
            float s = ((s0.x + s0.y) + (s0.z + s0.w))
                    + ((s1.x + s1.y) + (s1.z + s1.w))
                    + ((s2.x + s2.y) + (s2.z + s2.w))
                    + ((s3.x + s3.y) + (s3.z + s3.w));
            float yv = fmaf(sxc[buf][t][ddm], Dval, s);
            float zv = sz[buf][t][ddm];
            yv *= zv / (1.f + __expf(-zv));
            g_yact_h[(size_t)(b*SEQ + seg*SEGLEN + ch*32 + t)*DINNER + d0 + ddm] = __float2half(yv);
        }
    }
}

// ---------------- launch ----------------
extern "C" void kernel_launch(void* const* d_in, const int* in_sizes, int n_in,
                              void* d_out, int out_size)
{
    const float* x          = (const float*)d_in[0];
    const float* norm_w     = (const float*)d_in[1];
    const float* in_proj_w  = (const float*)d_in[2];
    const float* conv_w     = (const float*)d_in[3];
    const float* conv_b     = (const float*)d_in[4];
    const float* x_proj_w   = (const float*)d_in[5];
    const float* dt_proj_w  = (const float*)d_in[6];
    const float* dt_proj_b  = (const float*)d_in[7];
    const float* A_log      = (const float*)d_in[8];
    const float* Dp         = (const float*)d_in[9];
    const float* out_proj_w = (const float*)d_in[10];
    float* out = (float*)d_out;
    (void)in_sizes; (void)n_in; (void)out_size;

    __half *hn_h, *yact_h, *win_h, *wout_h;
    float *xz;
    cudaGetSymbolAddress((void**)&hn_h,   g_hn_h);
    cudaGetSymbolAddress((void**)&xz,     g_xz);
    cudaGetSymbolAddress((void**)&yact_h, g_yact_h);
    cudaGetSymbolAddress((void**)&win_h,  g_win_h);
    cudaGetSymbolAddress((void**)&wout_h, g_wout_h);

    const int SMEM = 46080;   // max(3*15360 pipeline, 33792 MODE1 transpose)
    const int XSMEM = (48*XPB + 2*320) * 4;
    cudaFuncSetAttribute(mma_pipe_h<0>, cudaFuncAttributeMaxDynamicSharedMemorySize, SMEM);
    cudaFuncSetAttribute(mma_pipe_h<1>, cudaFuncAttributeMaxDynamicSharedMemorySize, SMEM);
    cudaFuncSetAttribute(xproj_conv_kernel, cudaFuncAttributeMaxDynamicSharedMemorySize, XSMEM);

    // 1) rmsnorm + weight cvt
    rmsnorm_cvt_kernel<<<NTOK/32, 256>>>(x, norm_w, in_proj_w, out_proj_w, x_proj_w);
    // 2) xz = hn @ in_proj_w^T
    mma_pipe_h<0><<<dim3(32, 16), 256, SMEM>>>(hn_h, win_h, xz, DMODEL, 2*DINNER, nullptr);
    // 3+4+5) conv+silu + x_proj GEMM + delta/ddx epilogue (fused)
    xproj_conv_kernel<<<NTOK/16, 256, XSMEM>>>(conv_w, conv_b, dt_proj_w, dt_proj_b);
    // 6) segmented selective scan (2 kernels; part3 folds the carry)
    scan_part1<<<dim3(DINNER/8, NSEG, BATCH), 128>>>(A_log);
    scan_part3<<<dim3(DINNER/8, NSEG, BATCH), 128>>>(A_log, Dp);
    // 7) out = yact @ out_proj_w^T + residual
    mma_pipe_h<1><<<dim3(32, 4), 256, SMEM>>>(yact_h, wout_h, out, DINNER, DMODEL, x);
}

// round 15
// speedup vs baseline: 1.0035x; 1.0035x over previous
#include <cuda_runtime.h>
#include <cuda_fp16.h>
#include <math.h>

#define BATCH  2
#define SEQ    2048
#define DMODEL 256
#define DINNER 512
#define DSTATE 16
#define NTOK   (BATCH*SEQ)   // 4096
#define NSEG   8
#define SEGLEN (SEQ/NSEG)    // 256
#define NCHAIN (BATCH*DINNER*DSTATE)  // 16384

// ---------------- scratch ----------------
__device__ __half g_hn_h[NTOK*DMODEL];
__device__ float  g_xz[NTOK*2*DINNER];
__device__ float  g_xc[NTOK*DINNER];
__device__ float  g_dbl[NTOK*48];
__device__ float  g_ddx[NTOK*DINNER*2];    // (delta, delta*xc) pairs
__device__ __half g_yact_h[NTOK*DINNER];
__device__ __half g_win_h[2*DINNER*DMODEL];
__device__ __half g_wout_h[DMODEL*DINNER];
__device__ __half g_wxp_h[48*DINNER];
__device__ float  g_scanH[NSEG*NCHAIN];
__device__ float  g_scanP[NSEG*NCHAIN];

__device__ __forceinline__ void cpa16(unsigned dst, const void* src) {
    asm volatile("cp.async.ca.shared.global [%0], [%1], 16;\n" :: "r"(dst), "l"(src));
}
template<int N> __device__ __forceinline__ void waitg() {
    asm volatile("cp.async.wait_group %0;\n" :: "n"(N));
}

// ---------------- 1) RMSNorm + weight cvt ----------------
__global__ __launch_bounds__(256) void rmsnorm_cvt_kernel(
    const float* __restrict__ x, const float* __restrict__ nw,
    const float* __restrict__ win, const float* __restrict__ wout,
    const float* __restrict__ wxp)
{
    {
        int stride = 128*256;
        for (int i = blockIdx.x*256 + threadIdx.x; i < 2*DINNER*DMODEL; i += stride)
            g_win_h[i] = __float2half(win[i]);
        for (int i = blockIdx.x*256 + threadIdx.x; i < DMODEL*DINNER; i += stride)
            g_wout_h[i] = __float2half(wout[i]);
        for (int i = blockIdx.x*256 + threadIdx.x; i < 48*DINNER; i += stride)
            g_wxp_h[i] = __float2half(wxp[i]);
    }

    int l0 = blockIdx.x * 32;
    int b  = l0 >> 11;
    int lb = l0 & 2047;
    int w    = threadIdx.x >> 5;
    int lane = threadIdx.x & 31;

    __shared__ float st[256*33];
    __shared__ float ssum[32][9];
    __shared__ float rs[32];

    const float* xb = x + (size_t)b * DMODEL * SEQ + lb + lane;

    float vals[32];
    float ss = 0.f;
    #pragma unroll
    for (int ci = 0; ci < 32; ci++) {
        int c = ci*8 + w;
        float v = xb[(size_t)c * SEQ];
        vals[ci] = v;
        ss += v*v;
    }
    ssum[lane][w] = ss;
    __syncthreads();
    if (threadIdx.x < 32) {
        float tot = 0.f;
        #pragma unroll
        for (int j = 0; j < 8; j++) tot += ssum[threadIdx.x][j];
        rs[threadIdx.x] = rsqrtf(tot * (1.0f/DMODEL) + 1e-5f);
    }
    #pragma unroll
    for (int ci = 0; ci < 32; ci++)
        st[(ci*8 + w)*33 + lane] = vals[ci];
    __syncthreads();

    #pragma unroll
    for (int p = 0; p < 4; p++) {
        int t = (threadIdx.x >> 5) + p*8;
        float r = rs[t];
        __half* orow = g_hn_h + (size_t)(l0 + t)*DMODEL;
        #pragma unroll
        for (int j = 0; j < 8; j++) {
            int c = lane + j*32;
            orow[c] = __float2half(st[c*33 + t] * r * nw[c]);
        }
    }
}

// ---------------- fp16 tensor-core GEMM (race-safe 3-deep pipeline) ---------
#define HBUF 3840

template<int MODE>
__global__ __launch_bounds__(256) void mma_pipe_h(
    const __half* __restrict__ A, const __half* __restrict__ Bw,
    float* __restrict__ C, int K, int N, const float* __restrict__ resid)
{
    extern __shared__ __align__(16) unsigned sm[];
    int tid  = threadIdx.x;
    int lane = tid & 31, w = tid >> 5;
    int wm = w & 3, wn = w >> 2;
    int rowBase = blockIdx.x * 128;
    int colBase = blockIdx.y * 64;

    int arow = tid >> 1, aseg = tid & 1;
    int brow = tid >> 2, bseg = tid & 3;
    const __half* Ag = A  + (size_t)(rowBase + arow)*K + aseg*16;
    const __half* Bg = Bw + (size_t)(colBase + brow)*K + bseg*8;

    float acc[2][4][4];
    #pragma unroll
    for (int mt = 0; mt < 2; mt++)
        #pragma unroll
        for (int nt = 0; nt < 4; nt++)
            #pragma unroll
            for (int q = 0; q < 4; q++) acc[mt][nt][q] = 0.f;

    unsigned sbase = (unsigned)__cvta_generic_to_shared(sm);

    auto issue = [&](int kt, int buf) {
        unsigned ab = sbase + (unsigned)buf*15360u;
        cpa16(ab + (unsigned)(arow*80 + aseg*32),      Ag + kt);
        cpa16(ab + (unsigned)(arow*80 + aseg*32 + 16), Ag + kt + 8);
        cpa16(ab + 10240u + (unsigned)(brow*80 + bseg*16), Bg + kt);
        asm volatile("cp.async.commit_group;\n");
    };

    int CH = K >> 5;
    issue(0, 0);
    if (CH > 1) issue(32, 1);

    for (int c = 0; c < CH; c++) {
        if (c + 1 < CH) waitg<1>(); else waitg<0>();
        __syncthreads();
        // safe: buffer (c+2)%3 == (c-1)%3 was last read in chunk c-1,
        // and every thread passed this barrier after finishing it.
        if (c + 2 < CH) issue((c+2)*32, (c+2)%3);

        const unsigned* Asw = sm + (c%3)*HBUF;
        const unsigned* Bsw = Asw + 2560;

        #pragma unroll
        for (int ks = 0; ks < 2; ks++) {
            int kw = ks*8;
            unsigned a[2][4], bq[4][2];
            #pragma unroll
            for (int mt = 0; mt < 2; mt++) {
                int r0 = wm*32 + mt*16 + (lane >> 2);
                int bi = r0*20 + kw + (lane & 3);
                a[mt][0] = Asw[bi];
                a[mt][1] = Asw[bi + 160];
                a[mt][2] = Asw[bi + 4];
                a[mt][3] = Asw[bi + 164];
            }
            #pragma unroll
            for (int nt = 0; nt < 4; nt++) {
                int n0 = wn*32 + nt*8 + (lane >> 2);
                int bb = n0*20 + kw + (lane & 3);
                bq[nt][0] = Bsw[bb];
                bq[nt][1] = Bsw[bb + 4];
            }
            #pragma unroll
            for (int mt = 0; mt < 2; mt++)
                #pragma unroll
                for (int nt = 0; nt < 4; nt++)
                    asm volatile(
                        "mma.sync.aligned.m16n8k16.row.col.f32.f16.f16.f32 "
                        "{%0,%1,%2,%3}, {%4,%5,%6,%7}, {%8,%9}, {%0,%1,%2,%3};"
                        : "+f"(acc[mt][nt][0]), "+f"(acc[mt][nt][1]),
                          "+f"(acc[mt][nt][2]), "+f"(acc[mt][nt][3])
                        : "r"(a[mt][0]), "r"(a[mt][1]), "r"(a[mt][2]), "r"(a[mt][3]),
                          "r"(bq[nt][0]), "r"(bq[nt][1]));
        }
    }

    if (MODE == 0) {
        #pragma unroll
        for (int mt = 0; mt < 2; mt++) {
            #pragma unroll
            for (int nt = 0; nt < 4; nt++) {
                int r0 = rowBase + wm*32 + mt*16 + (lane >> 2);
                int c0 = colBase + wn*32 + nt*8 + (lane & 3)*2;
                *(float2*)&C[(size_t)r0*N + c0] =
                    make_float2(acc[mt][nt][0], acc[mt][nt][1]);
                *(float2*)&C[(size_t)(r0+8)*N + c0] =
                    make_float2(acc[mt][nt][2], acc[mt][nt][3]);
            }
        }
    } else {
        __syncthreads();   // all warps done reading As/Bs before reuse as tr
        float* tr = (float*)sm;
        #pragma unroll
        for (int mt = 0; mt < 2; mt++) {
            #pragma unroll
            for (int nt = 0; nt < 4; nt++) {
                int r  = wm*32 + mt*16 + (lane >> 2);
                int cl = wn*32 + nt*8 + (lane & 3)*2;
                tr[ cl   *132 + r    ] = acc[mt][nt][0];
                tr[(cl+1)*132 + r    ] = acc[mt][nt][1];
                tr[ cl   *132 + r + 8] = acc[mt][nt][2];
                tr[(cl+1)*132 + r + 8] = acc[mt][nt][3];
            }
        }
        __syncthreads();
        int b0 = rowBase >> 11;
        int lbase = rowBase & 2047;
        for (int i = tid; i < 64*32; i += 256) {
            int cl = i >> 5, j = i & 31;
            float4 v = *(float4*)&tr[cl*132 + j*4];
            size_t o = (size_t)b0*DMODEL*SEQ + (size_t)(colBase + cl)*SEQ + lbase + j*4;
            float4 rr = *(const float4*)&resid[o];
            v.x += rr.x; v.y += rr.y; v.z += rr.z; v.w += rr.w;
            *(float4*)&C[o] = v;
        }
    }
}

// ---------------- x_proj fused with conv+SiLU + delta/ddx epilogue ----------
#define XPB 260

__global__ __launch_bounds__(256) void xproj_conv_kernel(
    const float* __restrict__ cw, const float* __restrict__ cb,
    const float* __restrict__ dtW, const float* __restrict__ dtB)
{
    extern __shared__ __align__(16) unsigned xsm[];
    unsigned* Bs = xsm;
    unsigned* As = xsm + 48*XPB;
    __shared__ __align__(16) float sdt[16][20];

    int tid = threadIdx.x, lane = tid & 31, w = tid >> 5;
    int rowBase = blockIdx.x * 16;
    int l0 = rowBase & 2047;

    {
        unsigned bbase = (unsigned)__cvta_generic_to_shared(Bs);
        #pragma unroll
        for (int k = 0; k < 12; k++) {
            int i = tid + k*256;
            int n = i >> 6;
            int hw = (i & 63) * 4;
            cpa16(bbase + (unsigned)((n*XPB + hw)*4),
                  g_wxp_h + (size_t)n*DINNER + hw*2);
        }
        asm volatile("cp.async.commit_group;\n");
    }

    int tA = tid >> 4;
    int dOff = (tid & 15) * 2;
    int gt = rowBase + tA;

    float2 v[4];
    #pragma unroll
    for (int j = 0; j < 4; j++) {
        int ls = l0 + tA - 3 + j;
        v[j] = (ls >= 0) ? *(const float2*)(g_xz + (size_t)(gt-3+j)*1024 + dOff)
                         : make_float2(0.f, 0.f);
    }

    float acc[4] = {0.f, 0.f, 0.f, 0.f};

    waitg<0>();
    __syncthreads();

    for (int c = 0; c < 16; c++) {
        int d = c*32 + dOff;
        float4 w0 = *(const float4*)(cw + (size_t)d*4);
        float4 w1 = *(const float4*)(cw + (size_t)(d+1)*4);
        float2 a2 = *(const float2*)(cb + d);
        a2.x += w0.x*v[0].x + w0.y*v[1].x + w0.z*v[2].x + w0.w*v[3].x;
        a2.y += w1.x*v[0].y + w1.y*v[1].y + w1.z*v[2].y + w1.w*v[3].y;
        a2.x = a2.x / (1.f + __expf(-a2.x));
        a2.y = a2.y / (1.f + __expf(-a2.y));
        *(float2*)(g_xc + (size_t)gt*DINNER + d) = a2;

        unsigned* Ab = As + (c & 1)*320;
        __half2 p = __floats2half2_rn(a2.x, a2.y);
        Ab[tA*20 + (tid & 15)] = *(unsigned*)&p;

        if (c + 1 < 16) {
            int dn = (c+1)*32 + dOff;
            #pragma unroll
            for (int j = 0; j < 4; j++) {
                int ls = l0 + tA - 3 + j;
                v[j] = (ls >= 0) ? *(const float2*)(g_xz + (size_t)(gt-3+j)*1024 + dn)
                                 : make_float2(0.f, 0.f);
            }
        }
        __syncthreads();

        if (w < 6) {
            const unsigned* Asw = As + (c & 1)*320;
            #pragma unroll
            for (int ks = 0; ks < 2; ks++) {
                int kw = ks*8;
                unsigned a[4], bq[2];
                {
                    int r0 = lane >> 2;
                    int bi = r0*20 + kw + (lane & 3);
                    a[0] = Asw[bi];
                    a[1] = Asw[bi + 160];
                    a[2] = Asw[bi + 4];
                    a[3] = Asw[bi + 164];
                }
                {
                    int n0 = w*8 + (lane >> 2);
                    int bb = n0*XPB + c*16 + kw + (lane & 3);
                    bq[0] = Bs[bb];
                    bq[1] = Bs[bb + 4];
                }
                asm volatile(
                    "mma.sync.aligned.m16n8k16.row.col.f32.f16.f16.f32 "
                    "{%0,%1,%2,%3}, {%4,%5,%6,%7}, {%8,%9}, {%0,%1,%2,%3};"
                    : "+f"(acc[0]), "+f"(acc[1]), "+f"(acc[2]), "+f"(acc[3])
                    : "r"(a[0]), "r"(a[1]), "r"(a[2]), "r"(a[3]),
                      "r"(bq[0]), "r"(bq[1]));
            }
        }
    }

    if (w < 6) {
        int r0 = rowBase + (lane >> 2);
        int c0 = w*8 + (lane & 3)*2;
        *(float2*)&g_dbl[(size_t)r0*48 + c0] = make_float2(acc[0], acc[1]);
        *(float2*)&g_dbl[(size_t)(r0+8)*48 + c0] = make_float2(acc[2], acc[3]);
    }
    if (w < 2) {
        int tloc = lane >> 2;
        int c0 = w*8 + (lane & 3)*2;
        sdt[tloc    ][c0] = acc[0]; sdt[tloc    ][c0+1] = acc[1];
        sdt[tloc + 8][c0] = acc[2]; sdt[tloc + 8][c0+1] = acc[3];
    }
    __syncthreads();

    {
        int d2 = tid * 2;
        const float4* wr0 = (const float4*)(dtW + (size_t)d2*16);
        const float4* wr1 = (const float4*)(dtW + (size_t)(d2+1)*16);
        float4 A0 = wr0[0], A1 = wr0[1], A2 = wr0[2], A3 = wr0[3];
        float4 B0 = wr1[0], B1 = wr1[1], B2 = wr1[2], B3 = wr1[3];
        float b0 = dtB[d2], b1 = dtB[d2+1];
        #pragma unroll 4
        for (int t = 0; t < 16; t++) {
            const float4* sp = (const float4*)&sdt[t][0];
            float4 r0 = sp[0], r1 = sp[1], r2 = sp[2], r3 = sp[3];
            float a0 = b0, a1 = b1;
            a0 = fmaf(r0.x,A0.x,a0); a0 = fmaf(r0.y,A0.y,a0); a0 = fmaf(r0.z,A0.z,a0); a0 = fmaf(r0.w,A0.w,a0);
            a0 = fmaf(r1.x,A1.x,a0); a0 = fmaf(r1.y,A1.y,a0); a0 = fmaf(r1.z,A1.z,a0); a0 = fmaf(r1.w,A1.w,a0);
            a0 = fmaf(r2.x,A2.x,a0); a0 = fmaf(r2.y,A2.y,a0); a0 = fmaf(r2.z,A2.z,a0); a0 = fmaf(r2.w,A2.w,a0);
            a0 = fmaf(r3.x,A3.x,a0); a0 = fmaf(r3.y,A3.y,a0); a0 = fmaf(r3.z,A3.z,a0); a0 = fmaf(r3.w,A3.w,a0);
            a1 = fmaf(r0.x,B0.x,a1); a1 = fmaf(r0.y,B0.y,a1); a1 = fmaf(r0.z,B0.z,a1); a1 = fmaf(r0.w,B0.w,a1);
            a1 = fmaf(r1.x,B1.x,a1); a1 = fmaf(r1.y,B1.y,a1); a1 = fmaf(r1.z,B1.z,a1); a1 = fmaf(r1.w,B1.w,a1);
            a1 = fmaf(r2.x,B2.x,a1); a1 = fmaf(r2.y,B2.y,a1); a1 = fmaf(r2.z,B2.z,a1); a1 = fmaf(r2.w,B2.w,a1);
            a1 = fmaf(r3.x,B3.x,a1); a1 = fmaf(r3.y,B3.y,a1); a1 = fmaf(r3.z,B3.z,a1); a1 = fmaf(r3.w,B3.w,a1);
            a0 = (a0 > 20.f) ? a0 : log1pf(__expf(a0));
            a1 = (a1 > 20.f) ? a1 : log1pf(__expf(a1));
            float2 xcv = *(const float2*)(g_xc + (size_t)(rowBase + t)*DINNER + d2);
            float4 o = make_float4(a0, a0 * xcv.x, a1, a1 * xcv.y);
            *(float4*)(g_ddx + ((size_t)(rowBase + t)*DINNER + d2)*2) = o;
        }
    }
}

// ---------------- segmented selective scan (2 kernels, fused carry) ---------
// Phase 1: exact R12 version (double buffer, product P).
__global__ __launch_bounds__(128) void scan_part1(const float* __restrict__ A_log)
{
    int b   = blockIdx.z;
    int seg = blockIdx.y;
    int d0  = blockIdx.x * 8;
    int tid = threadIdx.x;
    int dl  = tid >> 4, n = tid & 15;
    int d   = d0 + dl;

    float a = -expf(A_log[d*DSTATE + n]);
    float h = 0.f, P = 1.f;

    __shared__ __align__(16) float sB[2][32][20];
    __shared__ __align__(16) float sddx[2][32][16];

    unsigned aB  = (unsigned)__cvta_generic_to_shared(&sB[0][0][0]);
    unsigned adx = (unsigned)__cvta_generic_to_shared(&sddx[0][0][0]);

    auto issue = [&](int ch, int buf) {
        int base = b*SEQ + seg*SEGLEN + ch*32;
        {
            int t = tid >> 2, s = tid & 3;
            cpa16(aB + (unsigned)((buf*32*20 + t*20 + s*4)*4),
                  g_dbl + (size_t)(base + t)*48 + 16 + s*4);
            cpa16(adx + (unsigned)((buf*32*16 + t*16 + s*4)*4),
                  g_ddx + ((size_t)(base + t)*DINNER + d0)*2 + s*4);
        }
        asm volatile("cp.async.commit_group;\n");
    };

    issue(0, 0);

    for (int ch = 0; ch < SEGLEN/32; ch++) {
        if (ch + 1 < SEGLEN/32) {
            issue(ch + 1, (ch + 1) & 1);
            waitg<1>();
        } else {
            waitg<0>();
        }
        __syncthreads();
        int buf = ch & 1;

        #pragma unroll
        for (int t = 0; t < 32; t++) {
            float2 ddx = *(const float2*)&sddx[buf][t][dl*2];
            float dA = __expf(ddx.x * a);
            h = fmaf(dA, h, ddx.y * sB[buf][t][n]);
            P *= dA;
        }
        __syncthreads();
    }

    int chain = (b*DINNER + d)*DSTATE + n;
    g_scanH[seg*NCHAIN + chain] = h;
    g_scanP[seg*NCHAIN + chain] = P;
}

// Phase 3: R12 version + inline carry prefix (no carry kernel).
__global__ __launch_bounds__(128) void scan_part3(
    const float* __restrict__ A_log, const float* __restrict__ Dp)
{
    int b   = blockIdx.z;
    int seg = blockIdx.y;
    int d0  = blockIdx.x * 8;
    int tid = threadIdx.x;
    int dl  = tid >> 4, n = tid & 15;
    int d   = d0 + dl;
    int ddm = tid & 7;

    float a = -expf(A_log[d*DSTATE + n]);
    float Dval = Dp[d0 + ddm];

    __shared__ __align__(16) float sBC[2][32][36];
    __shared__ __align__(16) float sddx[2][32][16];
    __shared__ float sxc[2][32][8];
    __shared__ float sz[2][32][8];
    __shared__ __align__(16) float shc[32][128];

    unsigned aBC = (unsigned)__cvta_generic_to_shared(&sBC[0][0][0]);
    unsigned adx = (unsigned)__cvta_generic_to_shared(&sddx[0][0][0]);
    unsigned axc = (unsigned)__cvta_generic_to_shared(&sxc[0][0][0]);
    unsigned az  = (unsigned)__cvta_generic_to_shared(&sz[0][0][0]);

    auto issue = [&](int ch, int buf) {
        int base = b*SEQ + seg*SEGLEN + ch*32;
        #pragma unroll
        for (int k = 0; k < 2; k++) {
            int i = tid + k*128;
            int t = i >> 3, s = i & 7;
            cpa16(aBC + (unsigned)((buf*32*36 + t*36 + s*4)*4),
                  g_dbl + (size_t)(base + t)*48 + 16 + s*4);
        }
        {
            int t = tid >> 2, s = tid & 3;
            cpa16(adx + (unsigned)((buf*32*16 + t*16 + s*4)*4),
                  g_ddx + ((size_t)(base + t)*DINNER + d0)*2 + s*4);
        }
        if (tid < 64) {
            int t = tid >> 1, hf = tid & 1;
            cpa16(axc + (unsigned)((buf*256 + t*8 + hf*4)*4),
                  g_xc + (size_t)(base + t)*DINNER + d0 + hf*4);
        } else {
            int i = tid - 64;
            int t = i >> 1, hf = i & 1;
            cpa16(az + (unsigned)((buf*256 + t*8 + hf*4)*4),
                  g_xz + (size_t)(base + t)*1024 + DINNER + d0 + hf*4);
        }
        asm volatile("cp.async.commit_group;\n");
    };

    issue(0, 0);

    // carry prefix: fold segments 0..seg-1 (overlaps the first cp.async)
    float h = 0.f;
    {
        int chain = (b*DINNER + d)*DSTATE + n;
        float Pv[NSEG-1], Hv[NSEG-1];
        #pragma unroll
        for (int s = 0; s < NSEG-1; s++) {
            bool m = (s < seg);
            Pv[s] = m ? g_scanP[s*NCHAIN + chain] : 1.f;
            Hv[s] = m ? g_scanH[s*NCHAIN + chain] : 0.f;
        }
        #pragma unroll
        for (int s = 0; s < NSEG-1; s++)
            h = fmaf(Pv[s], h, Hv[s]);
    }

    for (int ch = 0; ch < SEGLEN/32; ch++) {
        if (ch + 1 < SEGLEN/32) {
            issue(ch + 1, (ch + 1) & 1);
            waitg<1>();
        } else {
            waitg<0>();
        }
        __syncthreads();
        int buf = ch & 1;

        #pragma unroll
        for (int t = 0; t < 32; t++) {
            float2 ddx = *(const float2*)&sddx[buf][t][dl*2];
            float dA = __expf(ddx.x * a);
            h = fmaf(dA, h, ddx.y * sBC[buf][t][n]);
            shc[t][tid] = h * sBC[buf][t][16 + n];
        }
        __syncthreads();

        #pragma unroll
        for (int k = 0; k < 2; k++) {
            int t = (tid >> 3) + k*16;
            const float4* hp = (const float4*)&shc[t][ddm*16];
            float4 s0 = hp[0], s1 = hp[1], s2 = hp[2], s3 = hp[3];
            float s = ((s0.x + s0.y) + (s0.z + s0.w))
                    + ((s1.x + s1.y) + (s1.z + s1.w))
                    + ((s2.x + s2.y) + (s2.z + s2.w))
                    + ((s3.x + s3.y) + (s3.z + s3.w));
            float yv = fmaf(sxc[buf][t][ddm], Dval, s);
            float zv = sz[buf][t][ddm];
            yv *= zv / (1.f + __expf(-zv));
            g_yact_h[(size_t)(b*SEQ + seg*SEGLEN + ch*32 + t)*DINNER + d0 + ddm] = __float2half(yv);
        }
        __syncthreads();
    }
}

// ---------------- launch ----------------
extern "C" void kernel_launch(void* const* d_in, const int* in_sizes, int n_in,
                              void* d_out, int out_size)
{
    const float* x          = (const float*)d_in[0];
    const float* norm_w     = (const float*)d_in[1];
    const float* in_proj_w  = (const float*)d_in[2];
    const float* conv_w     = (const float*)d_in[3];
    const float* conv_b     = (const float*)d_in[4];
    const float* x_proj_w   = (const float*)d_in[5];
    const float* dt_proj_w  = (const float*)d_in[6];
    const float* dt_proj_b  = (const float*)d_in[7];
    const float* A_log      = (const float*)d_in[8];
    const float* Dp         = (const float*)d_in[9];
    const float* out_proj_w = (const float*)d_in[10];
    float* out = (float*)d_out;
    (void)in_sizes; (void)n_in; (void)out_size;

    __half *hn_h, *yact_h, *win_h, *wout_h;
    float *xz;
    cudaGetSymbolAddress((void**)&hn_h,   g_hn_h);
    cudaGetSymbolAddress((void**)&xz,     g_xz);
    cudaGetSymbolAddress((void**)&yact_h, g_yact_h);
    cudaGetSymbolAddress((void**)&win_h,  g_win_h);
    cudaGetSymbolAddress((void**)&wout_h, g_wout_h);

    const int SMEM = 46080;   // max(3*15360 pipeline, 33792 MODE1 transpose)
    const int XSMEM = (48*XPB + 2*320) * 4;
    cudaFuncSetAttribute(mma_pipe_h<0>, cudaFuncAttributeMaxDynamicSharedMemorySize, SMEM);
    cudaFuncSetAttribute(mma_pipe_h<1>, cudaFuncAttributeMaxDynamicSharedMemorySize, SMEM);
    cudaFuncSetAttribute(xproj_conv_kernel, cudaFuncAttributeMaxDynamicSharedMemorySize, XSMEM);

    // 1) rmsnorm + weight cvt
    rmsnorm_cvt_kernel<<<NTOK/32, 256>>>(x, norm_w, in_proj_w, out_proj_w, x_proj_w);
    // 2) xz = hn @ in_proj_w^T
    mma_pipe_h<0><<<dim3(32, 16), 256, SMEM>>>(hn_h, win_h, xz, DMODEL, 2*DINNER, nullptr);
    // 3+4+5) conv+silu + x_proj GEMM + delta/ddx epilogue (fused)
    xproj_conv_kernel<<<NTOK/16, 256, XSMEM>>>(conv_w, conv_b, dt_proj_w, dt_proj_b);
    // 6) segmented selective scan (2 kernels; part3 folds the carry inline)
    scan_part1<<<dim3(DINNER/8, NSEG, BATCH), 128>>>(A_log);
    scan_part3<<<dim3(DINNER/8, NSEG, BATCH), 128>>>(A_log, Dp);
    // 7) out = yact @ out_proj_w^T + residual
    mma_pipe_h<1><<<dim3(32, 4), 256, SMEM>>>(yact_h, wout_h, out, DINNER, DMODEL, x);
}

// round 16
// speedup vs baseline: 1.0673x; 1.0636x over previous
#include <cuda_runtime.h>
#include <cuda_fp16.h>
#include <math.h>

#define BATCH  2
#define SEQ    2048
#define DMODEL 256
#define DINNER 512
#define DSTATE 16
#define NTOK   (BATCH*SEQ)   // 4096
#define NSEG   8
#define SEGLEN (SEQ/NSEG)    // 256
#define NCHAIN (BATCH*DINNER*DSTATE)  // 16384

// ---------------- scratch ----------------
__device__ __half g_hn_h[NTOK*DMODEL];
__device__ __half g_xz_h[NTOK*2*DINNER];   // in_proj output (fp16)
__device__ __half g_xc_h[NTOK*DINNER];     // conv+silu output (fp16)
__device__ float  g_dbl[NTOK*48];
__device__ float  g_ddx[NTOK*DINNER*2];    // (delta, delta*xc) pairs (fp32)
__device__ __half g_yact_h[NTOK*DINNER];
__device__ __half g_win_h[2*DINNER*DMODEL];
__device__ __half g_wout_h[DMODEL*DINNER];
__device__ __half g_wxp_h[48*DINNER];
__device__ float  g_scanH[NSEG*NCHAIN];
__device__ float  g_scanP[NSEG*NCHAIN];

__device__ __forceinline__ void cpa16(unsigned dst, const void* src) {
    asm volatile("cp.async.ca.shared.global [%0], [%1], 16;\n" :: "r"(dst), "l"(src));
}
template<int N> __device__ __forceinline__ void waitg() {
    asm volatile("cp.async.wait_group %0;\n" :: "n"(N));
}

// ---------------- 1) RMSNorm + weight cvt ----------------
__global__ __launch_bounds__(256) void rmsnorm_cvt_kernel(
    const float* __restrict__ x, const float* __restrict__ nw,
    const float* __restrict__ win, const float* __restrict__ wout,
    const float* __restrict__ wxp)
{
    {
        int stride = 128*256;
        for (int i = blockIdx.x*256 + threadIdx.x; i < 2*DINNER*DMODEL; i += stride)
            g_win_h[i] = __float2half(win[i]);
        for (int i = blockIdx.x*256 + threadIdx.x; i < DMODEL*DINNER; i += stride)
            g_wout_h[i] = __float2half(wout[i]);
        for (int i = blockIdx.x*256 + threadIdx.x; i < 48*DINNER; i += stride)
            g_wxp_h[i] = __float2half(wxp[i]);
    }

    int l0 = blockIdx.x * 32;
    int b  = l0 >> 11;
    int lb = l0 & 2047;
    int w    = threadIdx.x >> 5;
    int lane = threadIdx.x & 31;

    __shared__ float st[256*33];
    __shared__ float ssum[32][9];
    __shared__ float rs[32];

    const float* xb = x + (size_t)b * DMODEL * SEQ + lb + lane;

    float vals[32];
    float ss = 0.f;
    #pragma unroll
    for (int ci = 0; ci < 32; ci++) {
        int c = ci*8 + w;
        float v = xb[(size_t)c * SEQ];
        vals[ci] = v;
        ss += v*v;
    }
    ssum[lane][w] = ss;
    __syncthreads();
    if (threadIdx.x < 32) {
        float tot = 0.f;
        #pragma unroll
        for (int j = 0; j < 8; j++) tot += ssum[threadIdx.x][j];
        rs[threadIdx.x] = rsqrtf(tot * (1.0f/DMODEL) + 1e-5f);
    }
    #pragma unroll
    for (int ci = 0; ci < 32; ci++)
        st[(ci*8 + w)*33 + lane] = vals[ci];
    __syncthreads();

    #pragma unroll
    for (int p = 0; p < 4; p++) {
        int t = (threadIdx.x >> 5) + p*8;
        float r = rs[t];
        __half* orow = g_hn_h + (size_t)(l0 + t)*DMODEL;
        #pragma unroll
        for (int j = 0; j < 8; j++) {
            int c = lane + j*32;
            orow[c] = __float2half(st[c*33 + t] * r * nw[c]);
        }
    }
}

// ---------------- fp16 tensor-core GEMM (race-safe 3-deep pipeline) ---------
// MODE 0: fp16 row-major store (in_proj). MODE 1: fp32 transpose+residual.
#define HBUF 3840

template<int MODE>
__global__ __launch_bounds__(256) void mma_pipe_h(
    const __half* __restrict__ A, const __half* __restrict__ Bw,
    void* __restrict__ Cv, int K, int N, const float* __restrict__ resid)
{
    extern __shared__ __align__(16) unsigned sm[];
    int tid  = threadIdx.x;
    int lane = tid & 31, w = tid >> 5;
    int wm = w & 3, wn = w >> 2;
    int rowBase = blockIdx.x * 128;
    int colBase = blockIdx.y * 64;

    int arow = tid >> 1, aseg = tid & 1;
    int brow = tid >> 2, bseg = tid & 3;
    const __half* Ag = A  + (size_t)(rowBase + arow)*K + aseg*16;
    const __half* Bg = Bw + (size_t)(colBase + brow)*K + bseg*8;

    float acc[2][4][4];
    #pragma unroll
    for (int mt = 0; mt < 2; mt++)
        #pragma unroll
        for (int nt = 0; nt < 4; nt++)
            #pragma unroll
            for (int q = 0; q < 4; q++) acc[mt][nt][q] = 0.f;

    unsigned sbase = (unsigned)__cvta_generic_to_shared(sm);

    auto issue = [&](int kt, int buf) {
        unsigned ab = sbase + (unsigned)buf*15360u;
        cpa16(ab + (unsigned)(arow*80 + aseg*32),      Ag + kt);
        cpa16(ab + (unsigned)(arow*80 + aseg*32 + 16), Ag + kt + 8);
        cpa16(ab + 10240u + (unsigned)(brow*80 + bseg*16), Bg + kt);
        asm volatile("cp.async.commit_group;\n");
    };

    int CH = K >> 5;
    issue(0, 0);
    if (CH > 1) issue(32, 1);

    for (int c = 0; c < CH; c++) {
        if (c + 1 < CH) waitg<1>(); else waitg<0>();
        __syncthreads();
        if (c + 2 < CH) issue((c+2)*32, (c+2)%3);

        const unsigned* Asw = sm + (c%3)*HBUF;
        const unsigned* Bsw = Asw + 2560;

        #pragma unroll
        for (int ks = 0; ks < 2; ks++) {
            int kw = ks*8;
            unsigned a[2][4], bq[4][2];
            #pragma unroll
            for (int mt = 0; mt < 2; mt++) {
                int r0 = wm*32 + mt*16 + (lane >> 2);
                int bi = r0*20 + kw + (lane & 3);
                a[mt][0] = Asw[bi];
                a[mt][1] = Asw[bi + 160];
                a[mt][2] = Asw[bi + 4];
                a[mt][3] = Asw[bi + 164];
            }
            #pragma unroll
            for (int nt = 0; nt < 4; nt++) {
                int n0 = wn*32 + nt*8 + (lane >> 2);
                int bb = n0*20 + kw + (lane & 3);
                bq[nt][0] = Bsw[bb];
                bq[nt][1] = Bsw[bb + 4];
            }
            #pragma unroll
            for (int mt = 0; mt < 2; mt++)
                #pragma unroll
                for (int nt = 0; nt < 4; nt++)
                    asm volatile(
                        "mma.sync.aligned.m16n8k16.row.col.f32.f16.f16.f32 "
                        "{%0,%1,%2,%3}, {%4,%5,%6,%7}, {%8,%9}, {%0,%1,%2,%3};"
                        : "+f"(acc[mt][nt][0]), "+f"(acc[mt][nt][1]),
                          "+f"(acc[mt][nt][2]), "+f"(acc[mt][nt][3])
                        : "r"(a[mt][0]), "r"(a[mt][1]), "r"(a[mt][2]), "r"(a[mt][3]),
                          "r"(bq[nt][0]), "r"(bq[nt][1]));
        }
    }

    if (MODE == 0) {
        __half* Ch = (__half*)Cv;
        #pragma unroll
        for (int mt = 0; mt < 2; mt++) {
            #pragma unroll
            for (int nt = 0; nt < 4; nt++) {
                int r0 = rowBase + wm*32 + mt*16 + (lane >> 2);
                int c0 = colBase + wn*32 + nt*8 + (lane & 3)*2;
                *(__half2*)&Ch[(size_t)r0*N + c0] =
                    __floats2half2_rn(acc[mt][nt][0], acc[mt][nt][1]);
                *(__half2*)&Ch[(size_t)(r0+8)*N + c0] =
                    __floats2half2_rn(acc[mt][nt][2], acc[mt][nt][3]);
            }
        }
    } else {
        float* C = (float*)Cv;
        __syncthreads();
        float* tr = (float*)sm;
        #pragma unroll
        for (int mt = 0; mt < 2; mt++) {
            #pragma unroll
            for (int nt = 0; nt < 4; nt++) {
                int r  = wm*32 + mt*16 + (lane >> 2);
                int cl = wn*32 + nt*8 + (lane & 3)*2;
                tr[ cl   *132 + r    ] = acc[mt][nt][0];
                tr[(cl+1)*132 + r    ] = acc[mt][nt][1];
                tr[ cl   *132 + r + 8] = acc[mt][nt][2];
                tr[(cl+1)*132 + r + 8] = acc[mt][nt][3];
            }
        }
        __syncthreads();
        int b0 = rowBase >> 11;
        int lbase = rowBase & 2047;
        for (int i = tid; i < 64*32; i += 256) {
            int cl = i >> 5, j = i & 31;
            float4 v = *(float4*)&tr[cl*132 + j*4];
            size_t o = (size_t)b0*DMODEL*SEQ + (size_t)(colBase + cl)*SEQ + lbase + j*4;
            float4 rr = *(const float4*)&resid[o];
            v.x += rr.x; v.y += rr.y; v.z += rr.z; v.w += rr.w;
            *(float4*)&C[o] = v;
        }
    }
}

// ---------------- x_proj fused with conv+SiLU + delta/ddx epilogue ----------
#define XPB 260

__global__ __launch_bounds__(256) void xproj_conv_kernel(
    const float* __restrict__ cw, const float* __restrict__ cb,
    const float* __restrict__ dtW, const float* __restrict__ dtB)
{
    extern __shared__ __align__(16) unsigned xsm[];
    unsigned* Bs = xsm;
    unsigned* As = xsm + 48*XPB;
    __shared__ __align__(16) float sdt[16][20];

    int tid = threadIdx.x, lane = tid & 31, w = tid >> 5;
    int rowBase = blockIdx.x * 16;
    int l0 = rowBase & 2047;

    {
        unsigned bbase = (unsigned)__cvta_generic_to_shared(Bs);
        #pragma unroll
        for (int k = 0; k < 12; k++) {
            int i = tid + k*256;
            int n = i >> 6;
            int hw = (i & 63) * 4;
            cpa16(bbase + (unsigned)((n*XPB + hw)*4),
                  g_wxp_h + (size_t)n*DINNER + hw*2);
        }
        asm volatile("cp.async.commit_group;\n");
    }

    int tA = tid >> 4;
    int dOff = (tid & 15) * 2;
    int gt = rowBase + tA;

    float2 v[4];
    #pragma unroll
    for (int j = 0; j < 4; j++) {
        int ls = l0 + tA - 3 + j;
        v[j] = (ls >= 0)
            ? __half22float2(*(const __half2*)(g_xz_h + (size_t)(gt-3+j)*1024 + dOff))
            : make_float2(0.f, 0.f);
    }

    float acc[4] = {0.f, 0.f, 0.f, 0.f};

    waitg<0>();
    __syncthreads();

    for (int c = 0; c < 16; c++) {
        int d = c*32 + dOff;
        float4 w0 = *(const float4*)(cw + (size_t)d*4);
        float4 w1 = *(const float4*)(cw + (size_t)(d+1)*4);
        float2 a2 = *(const float2*)(cb + d);
        a2.x += w0.x*v[0].x + w0.y*v[1].x + w0.z*v[2].x + w0.w*v[3].x;
        a2.y += w1.x*v[0].y + w1.y*v[1].y + w1.z*v[2].y + w1.w*v[3].y;
        a2.x = a2.x / (1.f + __expf(-a2.x));
        a2.y = a2.y / (1.f + __expf(-a2.y));

        __half2 p = __floats2half2_rn(a2.x, a2.y);
        *(__half2*)(g_xc_h + (size_t)gt*DINNER + d) = p;

        unsigned* Ab = As + (c & 1)*320;
        Ab[tA*20 + (tid & 15)] = *(unsigned*)&p;

        if (c + 1 < 16) {
            int dn = (c+1)*32 + dOff;
            #pragma unroll
            for (int j = 0; j < 4; j++) {
                int ls = l0 + tA - 3 + j;
                v[j] = (ls >= 0)
                    ? __half22float2(*(const __half2*)(g_xz_h + (size_t)(gt-3+j)*1024 + dn))
                    : make_float2(0.f, 0.f);
            }
        }
        __syncthreads();

        if (w < 6) {
            const unsigned* Asw = As + (c & 1)*320;
            #pragma unroll
            for (int ks = 0; ks < 2; ks++) {
                int kw = ks*8;
                unsigned a[4], bq[2];
                {
                    int r0 = lane >> 2;
                    int bi = r0*20 + kw + (lane & 3);
                    a[0] = Asw[bi];
                    a[1] = Asw[bi + 160];
                    a[2] = Asw[bi + 4];
                    a[3] = Asw[bi + 164];
                }
                {
                    int n0 = w*8 + (lane >> 2);
                    int bb = n0*XPB + c*16 + kw + (lane & 3);
                    bq[0] = Bs[bb];
                    bq[1] = Bs[bb + 4];
                }
                asm volatile(
                    "mma.sync.aligned.m16n8k16.row.col.f32.f16.f16.f32 "
                    "{%0,%1,%2,%3}, {%4,%5,%6,%7}, {%8,%9}, {%0,%1,%2,%3};"
                    : "+f"(acc[0]), "+f"(acc[1]), "+f"(acc[2]), "+f"(acc[3])
                    : "r"(a[0]), "r"(a[1]), "r"(a[2]), "r"(a[3]),
                      "r"(bq[0]), "r"(bq[1]));
            }
        }
    }

    if (w < 6) {
        int r0 = rowBase + (lane >> 2);
        int c0 = w*8 + (lane & 3)*2;
        *(float2*)&g_dbl[(size_t)r0*48 + c0] = make_float2(acc[0], acc[1]);
        *(float2*)&g_dbl[(size_t)(r0+8)*48 + c0] = make_float2(acc[2], acc[3]);
    }
    if (w < 2) {
        int tloc = lane >> 2;
        int c0 = w*8 + (lane & 3)*2;
        sdt[tloc    ][c0] = acc[0]; sdt[tloc    ][c0+1] = acc[1];
        sdt[tloc + 8][c0] = acc[2]; sdt[tloc + 8][c0+1] = acc[3];
    }
    __syncthreads();

    {
        int d2 = tid * 2;
        const float4* wr0 = (const float4*)(dtW + (size_t)d2*16);
        const float4* wr1 = (const float4*)(dtW + (size_t)(d2+1)*16);
        float4 A0 = wr0[0], A1 = wr0[1], A2 = wr0[2], A3 = wr0[3];
        float4 B0 = wr1[0], B1 = wr1[1], B2 = wr1[2], B3 = wr1[3];
        float b0 = dtB[d2], b1 = dtB[d2+1];
        #pragma unroll 4
        for (int t = 0; t < 16; t++) {
            const float4* sp = (const float4*)&sdt[t][0];
            float4 r0 = sp[0], r1 = sp[1], r2 = sp[2], r3 = sp[3];
            float a0 = b0, a1 = b1;
            a0 = fmaf(r0.x,A0.x,a0); a0 = fmaf(r0.y,A0.y,a0); a0 = fmaf(r0.z,A0.z,a0); a0 = fmaf(r0.w,A0.w,a0);
            a0 = fmaf(r1.x,A1.x,a0); a0 = fmaf(r1.y,A1.y,a0); a0 = fmaf(r1.z,A1.z,a0); a0 = fmaf(r1.w,A1.w,a0);
            a0 = fmaf(r2.x,A2.x,a0); a0 = fmaf(r2.y,A2.y,a0); a0 = fmaf(r2.z,A2.z,a0); a0 = fmaf(r2.w,A2.w,a0);
            a0 = fmaf(r3.x,A3.x,a0); a0 = fmaf(r3.y,A3.y,a0); a0 = fmaf(r3.z,A3.z,a0); a0 = fmaf(r3.w,A3.w,a0);
            a1 = fmaf(r0.x,B0.x,a1); a1 = fmaf(r0.y,B0.y,a1); a1 = fmaf(r0.z,B0.z,a1); a1 = fmaf(r0.w,B0.w,a1);
            a1 = fmaf(r1.x,B1.x,a1); a1 = fmaf(r1.y,B1.y,a1); a1 = fmaf(r1.z,B1.z,a1); a1 = fmaf(r1.w,B1.w,a1);
            a1 = fmaf(r2.x,B2.x,a1); a1 = fmaf(r2.y,B2.y,a1); a1 = fmaf(r2.z,B2.z,a1); a1 = fmaf(r2.w,B2.w,a1);
            a1 = fmaf(r3.x,B3.x,a1); a1 = fmaf(r3.y,B3.y,a1); a1 = fmaf(r3.z,B3.z,a1); a1 = fmaf(r3.w,B3.w,a1);
            a0 = (a0 > 20.f) ? a0 : log1pf(__expf(a0));
            a1 = (a1 > 20.f) ? a1 : log1pf(__expf(a1));
            float2 xcv = __half22float2(*(const __half2*)(g_xc_h + (size_t)(rowBase + t)*DINNER + d2));
            float4 o = make_float4(a0, a0 * xcv.x, a1, a1 * xcv.y);
            *(float4*)(g_ddx + ((size_t)(rowBase + t)*DINNER + d2)*2) = o;
        }
    }
}

// ---------------- segmented selective scan (2 kernels, fused carry) ---------
// Phase 1: single sync per chunk (issue after barrier).
__global__ __launch_bounds__(128) void scan_part1(const float* __restrict__ A_log)
{
    int b   = blockIdx.z;
    int seg = blockIdx.y;
    int d0  = blockIdx.x * 8;
    int tid = threadIdx.x;
    int dl  = tid >> 4, n = tid & 15;
    int d   = d0 + dl;

    float a = -expf(A_log[d*DSTATE + n]);
    float h = 0.f, P = 1.f;

    __shared__ __align__(16) float sB[2][32][20];
    __shared__ __align__(16) float sddx[2][32][16];

    unsigned aB  = (unsigned)__cvta_generic_to_shared(&sB[0][0][0]);
    unsigned adx = (unsigned)__cvta_generic_to_shared(&sddx[0][0][0]);

    auto issue = [&](int ch, int buf) {
        int base = b*SEQ + seg*SEGLEN + ch*32;
        {
            int t = tid >> 2, s = tid & 3;
            cpa16(aB + (unsigned)((buf*32*20 + t*20 + s*4)*4),
                  g_dbl + (size_t)(base + t)*48 + 16 + s*4);
            cpa16(adx + (unsigned)((buf*32*16 + t*16 + s*4)*4),
                  g_ddx + ((size_t)(base + t)*DINNER + d0)*2 + s*4);
        }
        asm volatile("cp.async.commit_group;\n");
    };

    issue(0, 0);

    for (int ch = 0; ch < SEGLEN/32; ch++) {
        waitg<0>();
        __syncthreads();
        if (ch + 1 < SEGLEN/32) issue(ch + 1, (ch + 1) & 1);
        int buf = ch & 1;

        #pragma unroll
        for (int t = 0; t < 32; t++) {
            float2 ddx = *(const float2*)&sddx[buf][t][dl*2];
            float dA = __expf(ddx.x * a);
            h = fmaf(dA, h, ddx.y * sB[buf][t][n]);
            P *= dA;
        }
    }

    int chain = (b*DINNER + d)*DSTATE + n;
    g_scanH[seg*NCHAIN + chain] = h;
    g_scanP[seg*NCHAIN + chain] = P;
}

// Phase 3: inline carry prefix, two syncs per chunk, fp16 xc/z.
__global__ __launch_bounds__(128) void scan_part3(
    const float* __restrict__ A_log, const float* __restrict__ Dp)
{
    int b   = blockIdx.z;
    int seg = blockIdx.y;
    int d0  = blockIdx.x * 8;
    int tid = threadIdx.x;
    int dl  = tid >> 4, n = tid & 15;
    int d   = d0 + dl;
    int ddm = tid & 7;

    float a = -expf(A_log[d*DSTATE + n]);
    float Dval = Dp[d0 + ddm];

    __shared__ __align__(16) float sBC[2][32][36];
    __shared__ __align__(16) float sddx[2][32][16];
    __shared__ __align__(16) __half sxc[2][32][8];
    __shared__ __align__(16) __half sz[2][32][8];
    __shared__ __align__(16) float shc[32][128];

    unsigned aBC = (unsigned)__cvta_generic_to_shared(&sBC[0][0][0]);
    unsigned adx = (unsigned)__cvta_generic_to_shared(&sddx[0][0][0]);
    unsigned axc = (unsigned)__cvta_generic_to_shared(&sxc[0][0][0]);
    unsigned az  = (unsigned)__cvta_generic_to_shared(&sz[0][0][0]);

    auto issue = [&](int ch, int buf) {
        int base = b*SEQ + seg*SEGLEN + ch*32;
        #pragma unroll
        for (int k = 0; k < 2; k++) {
            int i = tid + k*128;
            int t = i >> 3, s = i & 7;
            cpa16(aBC + (unsigned)((buf*32*36 + t*36 + s*4)*4),
                  g_dbl + (size_t)(base + t)*48 + 16 + s*4);
        }
        {
            int t = tid >> 2, s = tid & 3;
            cpa16(adx + (unsigned)((buf*32*16 + t*16 + s*4)*4),
                  g_ddx + ((size_t)(base + t)*DINNER + d0)*2 + s*4);
        }
        if (tid < 32) {
            cpa16(axc + (unsigned)((buf*256 + tid*8)*2),
                  g_xc_h + (size_t)(base + tid)*DINNER + d0);
        } else if (tid < 64) {
            int t = tid - 32;
            cpa16(az + (unsigned)((buf*256 + t*8)*2),
                  g_xz_h + (size_t)(base + t)*1024 + DINNER + d0);
        }
        asm volatile("cp.async.commit_group;\n");
    };

    issue(0, 0);

    // carry prefix: fold segments 0..seg-1 (overlaps the first cp.async)
    float h = 0.f;
    {
        int chain = (b*DINNER + d)*DSTATE + n;
        float Pv[NSEG-1], Hv[NSEG-1];
        #pragma unroll
        for (int s = 0; s < NSEG-1; s++) {
            bool m = (s < seg);
            Pv[s] = m ? g_scanP[s*NCHAIN + chain] : 1.f;
            Hv[s] = m ? g_scanH[s*NCHAIN + chain] : 0.f;
        }
        #pragma unroll
        for (int s = 0; s < NSEG-1; s++)
            h = fmaf(Pv[s], h, Hv[s]);
    }

    for (int ch = 0; ch < SEGLEN/32; ch++) {
        waitg<0>();
        __syncthreads();   // loads ready + prev reduce done (shc/buffers safe)
        if (ch + 1 < SEGLEN/32) issue(ch + 1, (ch + 1) & 1);
        int buf = ch & 1;

        #pragma unroll
        for (int t = 0; t < 32; t++) {
            float2 ddx = *(const float2*)&sddx[buf][t][dl*2];
            float dA = __expf(ddx.x * a);
            h = fmaf(dA, h, ddx.y * sBC[buf][t][n]);
            shc[t][tid] = h * sBC[buf][t][16 + n];
        }
        __syncthreads();

        #pragma unroll
        for (int k = 0; k < 2; k++) {
            int t = (tid >> 3) + k*16;
            const float4* hp = (const float4*)&shc[t][ddm*16];
            float4 s0 = hp[0], s1 = hp[1], s2 = hp[2], s3 = hp[3];
            float s = ((s0.x + s0.y) + (s0.z + s0.w))
                    + ((s1.x + s1.y) + (s1.z + s1.w))
                    + ((s2.x + s2.y) + (s2.z + s2.w))
                    + ((s3.x + s3.y) + (s3.z + s3.w));
            float xcv = __half2float(sxc[buf][t][ddm]);
            float zv  = __half2float(sz[buf][t][ddm]);
            float yv = fmaf(xcv, Dval, s);
            yv *= zv / (1.f + __expf(-zv));
            g_yact_h[(size_t)(b*SEQ + seg*SEGLEN + ch*32 + t)*DINNER + d0 + ddm] = __float2half(yv);
        }
    }
}

// ---------------- launch ----------------
extern "C" void kernel_launch(void* const* d_in, const int* in_sizes, int n_in,
                              void* d_out, int out_size)
{
    const float* x          = (const float*)d_in[0];
    const float* norm_w     = (const float*)d_in[1];
    const float* in_proj_w  = (const float*)d_in[2];
    const float* conv_w     = (const float*)d_in[3];
    const float* conv_b     = (const float*)d_in[4];
    const float* x_proj_w   = (const float*)d_in[5];
    const float* dt_proj_w  = (const float*)d_in[6];
    const float* dt_proj_b  = (const float*)d_in[7];
    const float* A_log      = (const float*)d_in[8];
    const float* Dp         = (const float*)d_in[9];
    const float* out_proj_w = (const float*)d_in[10];
    float* out = (float*)d_out;
    (void)in_sizes; (void)n_in; (void)out_size;

    __half *hn_h, *xz_h, *yact_h, *win_h, *wout_h;
    cudaGetSymbolAddress((void**)&hn_h,   g_hn_h);
    cudaGetSymbolAddress((void**)&xz_h,   g_xz_h);
    cudaGetSymbolAddress((void**)&yact_h, g_yact_h);
    cudaGetSymbolAddress((void**)&win_h,  g_win_h);
    cudaGetSymbolAddress((void**)&wout_h, g_wout_h);

    const int SMEM = 46080;   // max(3*15360 pipeline, 33792 MODE1 transpose)
    const int XSMEM = (48*XPB + 2*320) * 4;
    cudaFuncSetAttribute(mma_pipe_h<0>, cudaFuncAttributeMaxDynamicSharedMemorySize, SMEM);
    cudaFuncSetAttribute(mma_pipe_h<1>, cudaFuncAttributeMaxDynamicSharedMemorySize, SMEM);
    cudaFuncSetAttribute(xproj_conv_kernel, cudaFuncAttributeMaxDynamicSharedMemorySize, XSMEM);

    // 1) rmsnorm + weight cvt
    rmsnorm_cvt_kernel<<<NTOK/32, 256>>>(x, norm_w, in_proj_w, out_proj_w, x_proj_w);
    // 2) xz = hn @ in_proj_w^T (fp16 out)
    mma_pipe_h<0><<<dim3(32, 16), 256, SMEM>>>(hn_h, win_h, xz_h, DMODEL, 2*DINNER, nullptr);
    // 3+4+5) conv+silu + x_proj GEMM + delta/ddx epilogue (fused)
    xproj_conv_kernel<<<NTOK/16, 256, XSMEM>>>(conv_w, conv_b, dt_proj_w, dt_proj_b);
    // 6) segmented selective scan (2 kernels; part3 folds the carry inline)
    scan_part1<<<dim3(DINNER/8, NSEG, BATCH), 128>>>(A_log);
    scan_part3<<<dim3(DINNER/8, NSEG, BATCH), 128>>>(A_log, Dp);
    // 7) out = yact @ out_proj_w^T + residual
    mma_pipe_h<1><<<dim3(32, 4), 256, SMEM>>>(yact_h, wout_h, out, DINNER, DMODEL, x);
}